// round 2
// baseline (speedup 1.0000x reference)
#include <cuda_runtime.h>
#include <math.h>

#define T_   512
#define B_   256
#define DIN  85
#define H_   512
#define NOUT 33
#define G4   2048          // 4 gates * H, interleaved n = h*4 + g  (g: 0=i,1=f,2=o,3=c)
#define TB   (T_*B_)

// ---------------- scratch (device globals: allocation-free rule) ----------------
__device__ float g_xproj[(size_t)TB * G4];   // 1.07 GB: x-side gate pre-activations (+bias)
__device__ float g_hs[(size_t)TB * H_];      // 256 MB: hidden states for all t (ping chain + readout)
__device__ float g_C[B_ * H_];               // cell state (each (b,h) owned by one thread per step)
__device__ float g_zero[B_ * H_];            // zero-initialized, never written: H(-1)
__device__ float g_WxT[DIN * G4];            // packed, transposed input weights  [k][n]
__device__ float g_W4T[H_ * G4];             // packed, transposed recurrent weights [k][n]

// ---------------- weight repack: [g][h][k] -> [k][h*4+g] ----------------
__global__ void repack_wx(const float* __restrict__ Wxi, const float* __restrict__ Wxf,
                          const float* __restrict__ Wxo, const float* __restrict__ Wxc) {
    int idx = blockIdx.x * blockDim.x + threadIdx.x;
    if (idx >= DIN * G4) return;
    int k = idx / G4, n = idx % G4, h = n >> 2, g = n & 3;
    const float* W = (g == 0) ? Wxi : (g == 1) ? Wxf : (g == 2) ? Wxo : Wxc;
    g_WxT[idx] = W[h * DIN + k];
}
__global__ void repack_wh(const float* __restrict__ Whi, const float* __restrict__ Whf,
                          const float* __restrict__ Who, const float* __restrict__ Whc) {
    int idx = blockIdx.x * blockDim.x + threadIdx.x;
    if (idx >= H_ * G4) return;
    int k = idx / G4, n = idx % G4, h = n >> 2, g = n & 3;
    const float* W = (g == 0) ? Whi : (g == 1) ? Whf : (g == 2) ? Who : Whc;
    g_W4T[idx] = W[h * H_ + k];
}

// ---------------- input projections: [TB,85] x [85,2048] + bias ----------------
// block = 256 threads, tile 32 rows x 128 cols, K chunks of 32 (85 padded)
__global__ void xproj_kernel(const float* __restrict__ x,
                             const float* __restrict__ bhi, const float* __restrict__ bhf,
                             const float* __restrict__ bho, const float* __restrict__ bhc) {
    __shared__ float xs[32][33];
    __shared__ float ws[32][128];
    int row0 = blockIdx.y * 32;
    int col0 = blockIdx.x * 128;
    int tid  = threadIdx.x;
    int rb = tid >> 5, cb = tid & 31;
    float acc[4][4] = {};
    for (int kc = 0; kc < DIN; kc += 32) {
        for (int t2 = tid; t2 < 32 * 32; t2 += 256) {
            int r = t2 >> 5, k = t2 & 31, kk = kc + k;
            xs[r][k] = (kk < DIN) ? x[(size_t)(row0 + r) * DIN + kk] : 0.f;
        }
        for (int t2 = tid; t2 < 32 * 128; t2 += 256) {
            int k = t2 >> 7, c = t2 & 127, kk = kc + k;
            ws[k][c] = (kk < DIN) ? g_WxT[kk * G4 + col0 + c] : 0.f;
        }
        __syncthreads();
        #pragma unroll 8
        for (int k = 0; k < 32; k++) {
            float4 wv = ((const float4*)ws[k])[cb];
            #pragma unroll
            for (int i = 0; i < 4; i++) {
                float a = xs[rb * 4 + i][k];
                acc[i][0] += a * wv.x; acc[i][1] += a * wv.y;
                acc[i][2] += a * wv.z; acc[i][3] += a * wv.w;
            }
        }
        __syncthreads();
    }
    int n0 = col0 + cb * 4;
    int h  = n0 >> 2;
    float bi = bhi[h], bf = bhf[h], bo = bho[h], bc = bhc[h];
    #pragma unroll
    for (int i = 0; i < 4; i++) {
        int row = row0 + rb * 4 + i;
        float4 v = make_float4(acc[i][0] + bi, acc[i][1] + bf, acc[i][2] + bo, acc[i][3] + bc);
        *((float4*)&g_xproj[(size_t)row * G4 + n0]) = v;
    }
}

// ---------------- one recurrent step ----------------
// gates_pre[b,n] = xproj[t,b,n] + H(t-1)[b,:] . W4T[:,n];  then LSTM cell update.
// tile 32 batch-rows x 128 n-cols (= 32 h * 4 gates); each thread's 4 cols are
// the 4 gates of a single h -> cell update entirely in registers.
__global__ void step_kernel(int t) {
    __shared__ float hsm[32][65];
    __shared__ float ws[64][128];
    const float* Hprev = (t == 0) ? g_zero : &g_hs[(size_t)(t - 1) * B_ * H_];
    const float* xp    = &g_xproj[(size_t)t * B_ * G4];
    float* Hout        = &g_hs[(size_t)t * B_ * H_];
    int row0 = blockIdx.y * 32;    // batch
    int col0 = blockIdx.x * 128;   // n
    int tid  = threadIdx.x;
    int rb = tid >> 5, cb = tid & 31;
    float acc[4][4] = {};
    for (int kc = 0; kc < H_; kc += 64) {
        for (int t2 = tid; t2 < 32 * 64; t2 += 256) {
            int r = t2 >> 6, k = t2 & 63;
            hsm[r][k] = Hprev[(size_t)(row0 + r) * H_ + kc + k];
        }
        for (int t2 = tid; t2 < 64 * 128; t2 += 256) {
            int k = t2 >> 7, c = t2 & 127;
            ws[k][c] = g_W4T[(kc + k) * G4 + col0 + c];
        }
        __syncthreads();
        #pragma unroll 8
        for (int k = 0; k < 64; k++) {
            float4 wv = ((const float4*)ws[k])[cb];
            #pragma unroll
            for (int i = 0; i < 4; i++) {
                float a = hsm[rb * 4 + i][k];
                acc[i][0] += a * wv.x; acc[i][1] += a * wv.y;
                acc[i][2] += a * wv.z; acc[i][3] += a * wv.w;
            }
        }
        __syncthreads();
    }
    int n0 = col0 + cb * 4;
    int h  = n0 >> 2;
    #pragma unroll
    for (int i = 0; i < 4; i++) {
        int b = row0 + rb * 4 + i;
        float4 xv = *((const float4*)&xp[(size_t)b * G4 + n0]);
        float pi = acc[i][0] + xv.x;
        float pf = acc[i][1] + xv.y;
        float po = acc[i][2] + xv.z;
        float pc = acc[i][3] + xv.w;
        float I  = 1.f / (1.f + expf(-pi));
        float F  = 1.f / (1.f + expf(-pf));
        float O  = 1.f / (1.f + expf(-po));
        float Ch = tanhf(pc);
        float C  = (t == 0) ? (I * Ch) : fmaf(F, g_C[b * H_ + h], I * Ch);
        g_C[b * H_ + h] = C;
        Hout[b * H_ + h] = O * tanhf(C);
    }
}

// ---------------- readout: [TB,512] x [512,33] + bias ----------------
// block = 256 threads, 16 rows per block, h chunks of 128 staged in smem.
__global__ void readout_kernel(const float* __restrict__ Wro, const float* __restrict__ bro,
                               float* __restrict__ out) {
    __shared__ float rows[16][129];
    __shared__ float wsm[128][33];
    int row0 = blockIdx.x * 16;
    int tid  = threadIdx.x;
    float acc[3] = {0.f, 0.f, 0.f};
    for (int hc = 0; hc < H_; hc += 128) {
        for (int t2 = tid; t2 < 16 * 128; t2 += 256) {
            int r = t2 >> 7, k = t2 & 127;
            rows[r][k] = g_hs[(size_t)(row0 + r) * H_ + hc + k];
        }
        for (int t2 = tid; t2 < NOUT * 128; t2 += 256) {
            int o = t2 >> 7, k = t2 & 127;
            wsm[k][o] = Wro[o * H_ + hc + k];
        }
        __syncthreads();
        #pragma unroll
        for (int tk = 0; tk < 3; tk++) {
            int idx = tid + tk * 256;
            if (idx < 16 * NOUT) {
                int r = idx / NOUT, o = idx % NOUT;
                float s = 0.f;
                #pragma unroll 8
                for (int k = 0; k < 128; k++) s += rows[r][k] * wsm[k][o];
                acc[tk] += s;
            }
        }
        __syncthreads();
    }
    #pragma unroll
    for (int tk = 0; tk < 3; tk++) {
        int idx = tid + tk * 256;
        if (idx < 16 * NOUT) {
            int r = idx / NOUT, o = idx % NOUT;
            out[(size_t)(row0 + r) * NOUT + o] = acc[tk] + bro[o];
        }
    }
}

// ---------------- launch ----------------
extern "C" void kernel_launch(void* const* d_in, const int* in_sizes, int n_in,
                              void* d_out, int out_size) {
    const float* x   = (const float*)d_in[0];
    const float* Wxi = (const float*)d_in[1];
    const float* Wxf = (const float*)d_in[2];
    const float* Wxo = (const float*)d_in[3];
    const float* Wxc = (const float*)d_in[4];
    const float* Whi = (const float*)d_in[5];
    const float* bhi = (const float*)d_in[6];
    const float* Whf = (const float*)d_in[7];
    const float* bhf = (const float*)d_in[8];
    const float* Who = (const float*)d_in[9];
    const float* bho = (const float*)d_in[10];
    const float* Whc = (const float*)d_in[11];
    const float* bhc = (const float*)d_in[12];
    const float* Wro = (const float*)d_in[13];
    const float* bro = (const float*)d_in[14];
    float* out = (float*)d_out;

    repack_wx<<<(DIN * G4 + 255) / 256, 256>>>(Wxi, Wxf, Wxo, Wxc);
    repack_wh<<<(H_ * G4 + 255) / 256, 256>>>(Whi, Whf, Who, Whc);
    xproj_kernel<<<dim3(G4 / 128, TB / 32), 256>>>(x, bhi, bhf, bho, bhc);
    for (int t = 0; t < T_; t++)
        step_kernel<<<dim3(G4 / 128, B_ / 32), 256>>>(t);
    readout_kernel<<<TB / 16, 256>>>(Wro, bro, out);
}

// round 6
// speedup vs baseline: 4.1915x; 4.1915x over previous
#include <cuda_runtime.h>
#include <cuda_fp16.h>
#include <math.h>

#define T_   512
#define B_   256
#define DIN  85
#define H_   512
#define NOUT 33
#define G4   2048          // 4 gates * H, interleaved n = h*4+g (g: 0=i,1=f,2=o,3=c)
#define TB   (T_*B_)
#define KX   96            // DIN padded to multiple of 16

// ---------------- scratch (device globals) ----------------
__device__ float  g_xproj[(size_t)TB * G4];            // x-side preacts + bias (fp32)
__device__ __half g_hs[(size_t)TB * H_];               // hidden states fp16 (next-step A + readout)
__device__ float  g_C[B_ * H_];                        // cell state
__device__ __half g_zero[B_ * H_];                     // zeros: H(-1)
__device__ uint2  g_Wfrag[(G4/8) * (H_/16) * 32];      // recurrent W in mma B-frag layout [n8][ks][lane]
__device__ uint2  g_WxFrag[(G4/8) * (KX/16) * 32];     // input W frags [n8][ks(6)][lane]
__device__ float  g_bias4[G4];                         // packed biases per n
__device__ __half g_xh[(size_t)TB * KX];               // x cast to fp16, K padded

// ---------------- helpers ----------------
__device__ __forceinline__ unsigned smaddr(const void* p) {
    return (unsigned)__cvta_generic_to_shared(p);
}
#define CP16(dst, src) asm volatile("cp.async.ca.shared.global [%0], [%1], 16;\n" :: "r"(dst), "l"(src))
#define CP_COMMIT      asm volatile("cp.async.commit_group;\n")
#define CP_WAIT(N)     asm volatile("cp.async.wait_group %0;\n" :: "n"(N))

__device__ __forceinline__ void mma16816(float& d0, float& d1, float& d2, float& d3,
                                         unsigned a0, unsigned a1, unsigned a2, unsigned a3,
                                         unsigned b0, unsigned b1) {
    asm volatile("mma.sync.aligned.m16n8k16.row.col.f32.f16.f16.f32 "
                 "{%0,%1,%2,%3}, {%4,%5,%6,%7}, {%8,%9}, {%0,%1,%2,%3};\n"
                 : "+f"(d0), "+f"(d1), "+f"(d2), "+f"(d3)
                 : "r"(a0), "r"(a1), "r"(a2), "r"(a3), "r"(b0), "r"(b1));
}
__device__ __forceinline__ void ldmatrix4(unsigned& r0, unsigned& r1, unsigned& r2, unsigned& r3,
                                          unsigned addr) {
    asm volatile("ldmatrix.sync.aligned.m8n8.x4.shared.b16 {%0,%1,%2,%3}, [%4];\n"
                 : "=r"(r0), "=r"(r1), "=r"(r2), "=r"(r3) : "r"(addr));
}
__device__ __forceinline__ unsigned packh2(float a, float b) {
    __half2 h = __floats2half2_rn(a, b);
    return *reinterpret_cast<unsigned*>(&h);
}

// ---------------- weight repack into B-fragment layout ----------------
// mma m16n8k16 B frag (col-major): lane l holds halfs (k0,k0+1) and (k0+8,k0+9)
// with k0 = ks*16 + (l%4)*2, n = n8*8 + l/4.
__global__ void repack_wh_frag(const float* __restrict__ Whi, const float* __restrict__ Whf,
                               const float* __restrict__ Who, const float* __restrict__ Whc) {
    int idx = blockIdx.x * blockDim.x + threadIdx.x;
    if (idx >= (G4/8) * 32 * 32) return;
    int lane = idx & 31, ks = (idx >> 5) & 31, n8 = idx >> 10;
    int n = n8 * 8 + (lane >> 2), h = n >> 2, g = n & 3;
    int k0 = ks * 16 + (lane & 3) * 2;
    const float* W = (g == 0) ? Whi : (g == 1) ? Whf : (g == 2) ? Who : Whc;
    const float* Wr = W + (size_t)h * H_;
    uint2 v;
    v.x = packh2(Wr[k0],     Wr[k0 + 1]);
    v.y = packh2(Wr[k0 + 8], Wr[k0 + 9]);
    g_Wfrag[idx] = v;
}
__global__ void repack_wx_frag(const float* __restrict__ Wxi, const float* __restrict__ Wxf,
                               const float* __restrict__ Wxo, const float* __restrict__ Wxc) {
    int idx = blockIdx.x * blockDim.x + threadIdx.x;
    if (idx >= (G4/8) * 6 * 32) return;
    int lane = idx & 31, ks = (idx >> 5) % 6, n8 = idx / 192;
    int n = n8 * 8 + (lane >> 2), h = n >> 2, g = n & 3;
    int k0 = ks * 16 + (lane & 3) * 2;
    const float* W = (g == 0) ? Wxi : (g == 1) ? Wxf : (g == 2) ? Wxo : Wxc;
    const float* Wr = W + (size_t)h * DIN;
    float e0 = (k0     < DIN) ? Wr[k0]     : 0.f;
    float e1 = (k0 + 1 < DIN) ? Wr[k0 + 1] : 0.f;
    float e2 = (k0 + 8 < DIN) ? Wr[k0 + 8] : 0.f;
    float e3 = (k0 + 9 < DIN) ? Wr[k0 + 9] : 0.f;
    uint2 v; v.x = packh2(e0, e1); v.y = packh2(e2, e3);
    g_WxFrag[idx] = v;
}
__global__ void pack_bias(const float* __restrict__ bhi, const float* __restrict__ bhf,
                          const float* __restrict__ bho, const float* __restrict__ bhc) {
    int n = blockIdx.x * blockDim.x + threadIdx.x;
    if (n >= G4) return;
    int h = n >> 2, g = n & 3;
    g_bias4[n] = (g == 0) ? bhi[h] : (g == 1) ? bhf[h] : (g == 2) ? bho[h] : bhc[h];
}
__global__ void xcast_kernel(const float* __restrict__ x) {
    int idx = blockIdx.x * blockDim.x + threadIdx.x;
    if (idx >= TB * KX) return;
    int row = idx / KX, col = idx % KX;
    g_xh[idx] = __float2half_rn((col < DIN) ? x[(size_t)row * DIN + col] : 0.f);
}

// ---------------- x projection via mma: [TB,96]x[96,2048] + bias ----------------
__global__ __launch_bounds__(256) void xproj_kernel() {
    __shared__ __half As[64][104];
    int row0 = blockIdx.y * 64;
    int col0 = blockIdx.x * 64;
    int tid = threadIdx.x, lane = tid & 31, wid = tid >> 5;
    int wm = wid >> 1, wn = wid & 1;

    for (int i = tid; i < 64 * 12; i += 256) {  // 64 rows x 12 uint4
        int r = i / 12, q = i % 12;
        *(uint4*)&As[r][q * 8] = *(const uint4*)&g_xh[(size_t)(row0 + r) * KX + q * 8];
    }
    __syncthreads();

    float acc[4][4] = {};
    int arow = wm * 16 + (lane & 15);
    int acol = (lane & 16) ? 8 : 0;
    int n8base = blockIdx.x * 8 + wn * 4;
    #pragma unroll
    for (int ks = 0; ks < 6; ks++) {
        unsigned a0, a1, a2, a3;
        ldmatrix4(a0, a1, a2, a3, smaddr(&As[arow][ks * 16 + acol]));
        #pragma unroll
        for (int j = 0; j < 4; j++) {
            uint2 b = g_WxFrag[((n8base + j) * 6 + ks) * 32 + lane];
            mma16816(acc[j][0], acc[j][1], acc[j][2], acc[j][3], a0, a1, a2, a3, b.x, b.y);
        }
    }
    int r0 = row0 + wm * 16 + (lane >> 2);
    #pragma unroll
    for (int j = 0; j < 4; j++) {
        int n = col0 + wn * 32 + j * 8 + (lane & 3) * 2;
        float bx = g_bias4[n], by = g_bias4[n + 1];
        float2 v0 = make_float2(acc[j][0] + bx, acc[j][1] + by);
        float2 v1 = make_float2(acc[j][2] + bx, acc[j][3] + by);
        *(float2*)&g_xproj[(size_t)r0 * G4 + n]       = v0;
        *(float2*)&g_xproj[(size_t)(r0 + 8) * G4 + n] = v1;
    }
}

// ---------------- one recurrent step via mma ----------------
// gates_pre = xproj[t] + H(t-1) @ W4T; BM=64, BN=64, KC=64 double-buffered.
__global__ __launch_bounds__(256) void step_kernel(int t) {
    __shared__ union {
        struct { __half A[2][64][72]; uint4 B4[2][4][8][16]; } mm;
        float C[64][68];
    } sm;
    const __half* Hprev = (t == 0) ? g_zero : &g_hs[(size_t)(t - 1) * B_ * H_];
    int row0 = blockIdx.y * 64;  // batch
    int col0 = blockIdx.x * 64;  // n
    int tid = threadIdx.x, lane = tid & 31, wid = tid >> 5;
    int wm = wid >> 1, wn = wid & 1;

    // chunk loader: A tile (64x64 halfs) + B frags (4 ksteps x 8 n8frags x 256B)
    auto load_chunk = [&](int kc, int buf) {
        #pragma unroll
        for (int i = 0; i < 2; i++) {
            int idx = tid + i * 256;                       // 512 A segments
            int r = idx >> 3, q = idx & 7;
            CP16(smaddr(&sm.mm.A[buf][r][q * 8]),
                 Hprev + (size_t)(row0 + r) * H_ + kc * 64 + q * 8);
        }
        #pragma unroll
        for (int i = 0; i < 2; i++) {
            int idx = tid + i * 256;                       // 512 B segments
            int frag = idx >> 4, q = idx & 15;
            int j = frag & 7, ksl = frag >> 3;
            int n8 = blockIdx.x * 8 + j, ksg = kc * 4 + ksl;
            CP16(smaddr(&sm.mm.B4[buf][ksl][j][q]),
                 (const uint4*)g_Wfrag + ((size_t)(n8 * 32 + ksg)) * 16 + q);
        }
    };

    float acc[4][4] = {};
    int arow = wm * 16 + (lane & 15);
    int acol = (lane & 16) ? 8 : 0;

    load_chunk(0, 0); CP_COMMIT;
    int buf = 0;
    for (int kc = 0; kc < 8; kc++) {
        if (kc < 7) { load_chunk(kc + 1, buf ^ 1); CP_COMMIT; CP_WAIT(1); }
        else        { CP_WAIT(0); }
        __syncthreads();
        #pragma unroll
        for (int ksl = 0; ksl < 4; ksl++) {
            unsigned a0, a1, a2, a3;
            ldmatrix4(a0, a1, a2, a3, smaddr(&sm.mm.A[buf][arow][ksl * 16 + acol]));
            #pragma unroll
            for (int j = 0; j < 4; j++) {
                uint2 b = ((const uint2*)&sm.mm.B4[buf][ksl][wn * 4 + j][0])[lane];
                mma16816(acc[j][0], acc[j][1], acc[j][2], acc[j][3], a0, a1, a2, a3, b.x, b.y);
            }
        }
        __syncthreads();
        buf ^= 1;
    }

    // dump accum to smem (union reuse: all mma done, all warps synced above)
    int crow = wm * 16 + (lane >> 2);
    #pragma unroll
    for (int j = 0; j < 4; j++) {
        int c = wn * 32 + j * 8 + (lane & 3) * 2;
        *(float2*)&sm.C[crow][c]     = make_float2(acc[j][0], acc[j][1]);
        *(float2*)&sm.C[crow + 8][c] = make_float2(acc[j][2], acc[j][3]);
    }
    __syncthreads();

    // LSTM cell update: 512 h-pairs, 2 per thread
    const float* xp = g_xproj + (size_t)t * B_ * G4;
    __half* Hout = &g_hs[(size_t)t * B_ * H_];
    #pragma unroll
    for (int i = 0; i < 2; i++) {
        int p = tid + i * 256;
        int bi = p >> 3, hp = p & 7;
        int b = row0 + bi;
        int hg0 = blockIdx.x * 16 + hp * 2;   // global h of first of the pair
        float4 c0 = *(const float4*)&sm.C[bi][hp * 8];
        float4 c1 = *(const float4*)&sm.C[bi][hp * 8 + 4];
        float4 x0 = *(const float4*)&xp[(size_t)b * G4 + col0 + hp * 8];
        float4 x1 = *(const float4*)&xp[(size_t)b * G4 + col0 + hp * 8 + 4];
        float pi0 = c0.x + x0.x, pf0 = c0.y + x0.y, po0 = c0.z + x0.z, pc0 = c0.w + x0.w;
        float pi1 = c1.x + x1.x, pf1 = c1.y + x1.y, po1 = c1.z + x1.z, pc1 = c1.w + x1.w;
        float I0 = 1.f / (1.f + __expf(-pi0)), F0 = 1.f / (1.f + __expf(-pf0));
        float O0 = 1.f / (1.f + __expf(-po0)), Ch0 = tanhf(pc0);
        float I1 = 1.f / (1.f + __expf(-pi1)), F1 = 1.f / (1.f + __expf(-pf1));
        float O1 = 1.f / (1.f + __expf(-po1)), Ch1 = tanhf(pc1);
        float C0, C1;
        if (t == 0) { C0 = I0 * Ch0; C1 = I1 * Ch1; }
        else {
            float2 Cp = *(const float2*)&g_C[b * H_ + hg0];
            C0 = fmaf(F0, Cp.x, I0 * Ch0);
            C1 = fmaf(F1, Cp.y, I1 * Ch1);
        }
        *(float2*)&g_C[b * H_ + hg0] = make_float2(C0, C1);
        __half2 hv = __floats2half2_rn(O0 * tanhf(C0), O1 * tanhf(C1));
        *(__half2*)&Hout[b * H_ + hg0] = hv;
    }
}

// ---------------- readout: [TB,512] x [512,33] + bias ----------------
__global__ __launch_bounds__(256) void readout_kernel(const float* __restrict__ Wro,
                                                      const float* __restrict__ bro,
                                                      float* __restrict__ out) {
    __shared__ float rows[16][129];
    __shared__ float wsm[128][33];
    int row0 = blockIdx.x * 16;
    int tid = threadIdx.x;
    float acc[3] = {0.f, 0.f, 0.f};
    for (int hc = 0; hc < H_; hc += 128) {
        for (int t2 = tid; t2 < 16 * 128; t2 += 256) {
            int r = t2 >> 7, k = t2 & 127;
            rows[r][k] = __half2float(g_hs[(size_t)(row0 + r) * H_ + hc + k]);
        }
        for (int t2 = tid; t2 < NOUT * 128; t2 += 256) {
            int o = t2 >> 7, k = t2 & 127;
            wsm[k][o] = Wro[o * H_ + hc + k];
        }
        __syncthreads();
        #pragma unroll
        for (int tk = 0; tk < 3; tk++) {
            int idx = tid + tk * 256;
            if (idx < 16 * NOUT) {
                int r = idx / NOUT, o = idx % NOUT;
                float s = 0.f;
                #pragma unroll 8
                for (int k = 0; k < 128; k++) s += rows[r][k] * wsm[k][o];
                acc[tk] += s;
            }
        }
        __syncthreads();
    }
    #pragma unroll
    for (int tk = 0; tk < 3; tk++) {
        int idx = tid + tk * 256;
        if (idx < 16 * NOUT) {
            int r = idx / NOUT, o = idx % NOUT;
            out[(size_t)(row0 + r) * NOUT + o] = acc[tk] + bro[o];
        }
    }
}

// ---------------- launch ----------------
extern "C" void kernel_launch(void* const* d_in, const int* in_sizes, int n_in,
                              void* d_out, int out_size) {
    const float* x   = (const float*)d_in[0];
    const float* Wxi = (const float*)d_in[1];
    const float* Wxf = (const float*)d_in[2];
    const float* Wxo = (const float*)d_in[3];
    const float* Wxc = (const float*)d_in[4];
    const float* Whi = (const float*)d_in[5];
    const float* bhi = (const float*)d_in[6];
    const float* Whf = (const float*)d_in[7];
    const float* bhf = (const float*)d_in[8];
    const float* Who = (const float*)d_in[9];
    const float* bho = (const float*)d_in[10];
    const float* Whc = (const float*)d_in[11];
    const float* bhc = (const float*)d_in[12];
    const float* Wro = (const float*)d_in[13];
    const float* bro = (const float*)d_in[14];
    float* out = (float*)d_out;

    repack_wh_frag<<<(G4/8) * 32 * 32 / 256, 256>>>(Whi, Whf, Who, Whc);
    repack_wx_frag<<<((G4/8) * 6 * 32 + 255) / 256, 256>>>(Wxi, Wxf, Wxo, Wxc);
    pack_bias<<<G4 / 256, 256>>>(bhi, bhf, bho, bhc);
    xcast_kernel<<<(TB * KX + 255) / 256, 256>>>(x);
    xproj_kernel<<<dim3(G4 / 64, TB / 64), 256>>>();
    for (int t = 0; t < T_; t++)
        step_kernel<<<dim3(G4 / 64, B_ / 64), 256>>>(t);
    readout_kernel<<<TB / 16, 256>>>(Wro, bro, out);
}

// round 8
// speedup vs baseline: 5.1122x; 1.2197x over previous
#include <cuda_runtime.h>
#include <cuda_fp16.h>
#include <math.h>

#define T_   512
#define B_   256
#define DIN  85
#define H_   512
#define NOUT 33
#define G4   2048          // 4 gates * H, interleaved n = h*4+g (g: 0=i,1=f,2=o,3=c)
#define TB   (T_*B_)
#define KX   96            // DIN padded to multiple of 16
#define BM   64
#define BN   64

// ---------------- scratch (device globals) ----------------
__device__ float  g_xproj[(size_t)TB * G4];            // x-side preacts + bias (fp32)
__device__ __half g_hs[(size_t)TB * H_];               // hidden states fp16
__device__ uint2  g_Wfrag[(G4/8) * (H_/16) * 32];      // recurrent W frags [n8][ks][lane]
__device__ uint2  g_WxFrag[(G4/8) * (KX/16) * 32];     // input W frags [n8][ks(6)][lane]
__device__ float  g_bias4[G4];                         // packed biases per n
__device__ __half g_xh[(size_t)TB * KX];               // x cast to fp16, K padded
__device__ unsigned g_bar[T_][4];                      // per-step, per-rowblock arrival counters (zero)
__device__ unsigned g_done[4];                         // end-of-run counters (zero)

// ---------------- helpers ----------------
__device__ __forceinline__ unsigned smaddr(const void* p) {
    return (unsigned)__cvta_generic_to_shared(p);
}
#define CPG16(dst, src) asm volatile("cp.async.cg.shared.global [%0], [%1], 16;\n" :: "r"(dst), "l"(src))
#define CPA16(dst, src) asm volatile("cp.async.ca.shared.global [%0], [%1], 16;\n" :: "r"(dst), "l"(src))
#define CP_COMMIT       asm volatile("cp.async.commit_group;\n")
#define CP_WAIT(N)      asm volatile("cp.async.wait_group %0;\n" :: "n"(N))

__device__ __forceinline__ void mma16816(float& d0, float& d1, float& d2, float& d3,
                                         unsigned a0, unsigned a1, unsigned a2, unsigned a3,
                                         unsigned b0, unsigned b1) {
    asm volatile("mma.sync.aligned.m16n8k16.row.col.f32.f16.f16.f32 "
                 "{%0,%1,%2,%3}, {%4,%5,%6,%7}, {%8,%9}, {%0,%1,%2,%3};\n"
                 : "+f"(d0), "+f"(d1), "+f"(d2), "+f"(d3)
                 : "r"(a0), "r"(a1), "r"(a2), "r"(a3), "r"(b0), "r"(b1));
}
__device__ __forceinline__ void ldmatrix4(unsigned& r0, unsigned& r1, unsigned& r2, unsigned& r3,
                                          unsigned addr) {
    asm volatile("ldmatrix.sync.aligned.m8n8.x4.shared.b16 {%0,%1,%2,%3}, [%4];\n"
                 : "=r"(r0), "=r"(r1), "=r"(r2), "=r"(r3) : "r"(addr));
}
__device__ __forceinline__ unsigned packh2(float a, float b) {
    __half2 h = __floats2half2_rn(a, b);
    return *reinterpret_cast<unsigned*>(&h);
}

// ---------------- weight repack into B-fragment layout ----------------
__global__ void repack_wh_frag(const float* __restrict__ Whi, const float* __restrict__ Whf,
                               const float* __restrict__ Who, const float* __restrict__ Whc) {
    int idx = blockIdx.x * blockDim.x + threadIdx.x;
    if (idx >= (G4/8) * 32 * 32) return;
    int lane = idx & 31, ks = (idx >> 5) & 31, n8 = idx >> 10;
    int n = n8 * 8 + (lane >> 2), h = n >> 2, g = n & 3;
    int k0 = ks * 16 + (lane & 3) * 2;
    const float* W = (g == 0) ? Whi : (g == 1) ? Whf : (g == 2) ? Who : Whc;
    const float* Wr = W + (size_t)h * H_;
    uint2 v;
    v.x = packh2(Wr[k0],     Wr[k0 + 1]);
    v.y = packh2(Wr[k0 + 8], Wr[k0 + 9]);
    g_Wfrag[idx] = v;
}
__global__ void repack_wx_frag(const float* __restrict__ Wxi, const float* __restrict__ Wxf,
                               const float* __restrict__ Wxo, const float* __restrict__ Wxc) {
    int idx = blockIdx.x * blockDim.x + threadIdx.x;
    if (idx >= (G4/8) * 6 * 32) return;
    int lane = idx & 31, ks = (idx >> 5) % 6, n8 = idx / 192;
    int n = n8 * 8 + (lane >> 2), h = n >> 2, g = n & 3;
    int k0 = ks * 16 + (lane & 3) * 2;
    const float* W = (g == 0) ? Wxi : (g == 1) ? Wxf : (g == 2) ? Wxo : Wxc;
    const float* Wr = W + (size_t)h * DIN;
    float e0 = (k0     < DIN) ? Wr[k0]     : 0.f;
    float e1 = (k0 + 1 < DIN) ? Wr[k0 + 1] : 0.f;
    float e2 = (k0 + 8 < DIN) ? Wr[k0 + 8] : 0.f;
    float e3 = (k0 + 9 < DIN) ? Wr[k0 + 9] : 0.f;
    uint2 v; v.x = packh2(e0, e1); v.y = packh2(e2, e3);
    g_WxFrag[idx] = v;
}
__global__ void pack_bias(const float* __restrict__ bhi, const float* __restrict__ bhf,
                          const float* __restrict__ bho, const float* __restrict__ bhc) {
    int n = blockIdx.x * blockDim.x + threadIdx.x;
    if (n >= G4) return;
    int h = n >> 2, g = n & 3;
    g_bias4[n] = (g == 0) ? bhi[h] : (g == 1) ? bhf[h] : (g == 2) ? bho[h] : bhc[h];
}
__global__ void xcast_kernel(const float* __restrict__ x) {
    int idx = blockIdx.x * blockDim.x + threadIdx.x;
    if (idx >= TB * KX) return;
    int row = idx / KX, col = idx % KX;
    g_xh[idx] = __float2half_rn((col < DIN) ? x[(size_t)row * DIN + col] : 0.f);
}

// ---------------- x projection via mma: [TB,96]x[96,2048] + bias ----------------
__global__ __launch_bounds__(256) void xproj_kernel() {
    __shared__ __half As[64][104];
    int row0 = blockIdx.y * 64;
    int col0 = blockIdx.x * 64;
    int tid = threadIdx.x, lane = tid & 31, wid = tid >> 5;
    int wm = wid >> 1, wn = wid & 1;

    for (int i = tid; i < 64 * 12; i += 256) {
        int r = i / 12, q = i % 12;
        *(uint4*)&As[r][q * 8] = *(const uint4*)&g_xh[(size_t)(row0 + r) * KX + q * 8];
    }
    __syncthreads();

    float acc[4][4] = {};
    int arow = wm * 16 + (lane & 15);
    int acol = (lane & 16) ? 8 : 0;
    int n8base = blockIdx.x * 8 + wn * 4;
    #pragma unroll
    for (int ks = 0; ks < 6; ks++) {
        unsigned a0, a1, a2, a3;
        ldmatrix4(a0, a1, a2, a3, smaddr(&As[arow][ks * 16 + acol]));
        #pragma unroll
        for (int j = 0; j < 4; j++) {
            uint2 b = g_WxFrag[((n8base + j) * 6 + ks) * 32 + lane];
            mma16816(acc[j][0], acc[j][1], acc[j][2], acc[j][3], a0, a1, a2, a3, b.x, b.y);
        }
    }
    int r0 = row0 + wm * 16 + (lane >> 2);
    #pragma unroll
    for (int j = 0; j < 4; j++) {
        int n = col0 + wn * 32 + j * 8 + (lane & 3) * 2;
        float bx = g_bias4[n], by = g_bias4[n + 1];
        float2 v0 = make_float2(acc[j][0] + bx, acc[j][1] + by);
        float2 v1 = make_float2(acc[j][2] + bx, acc[j][3] + by);
        *(float2*)&g_xproj[(size_t)r0 * G4 + n]       = v0;
        *(float2*)&g_xproj[(size_t)(r0 + 8) * G4 + n] = v1;
    }
}

// ---------------- persistent recurrence kernel ----------------
// grid (32, 4): 128 blocks, 1/SM. Block (rb,cb): batch rows [rb*64,+64),
// n cols [cb*64,+64) == h [cb*16,+16). Weights resident in smem for all T.
// Cross-step sync: per-rb 32-arrival barrier on g_bar[t][rb].
#define SMEM_B_BYTES 65536                       // 8 n8frags x 32 ks x 256B
#define SMEM_A_BYTES (64 * 520 * 2)              // A tile 64x512 halfs, +8 pad/row
#define SMEM_TOTAL   (SMEM_B_BYTES + SMEM_A_BYTES)

__global__ __launch_bounds__(256, 1) void lstm_persistent() {
    extern __shared__ char smraw[];
    uint4*  Bsm = (uint4*)smraw;                       // [ (ks*8+j)*16 + q ]
    __half* Asm = (__half*)(smraw + SMEM_B_BYTES);     // [64][520]
    float*  Csm = (float*)(smraw + SMEM_B_BYTES);      // overlay [64][68]

    const int tid = threadIdx.x, lane = tid & 31, wid = tid >> 5;
    const int wm = wid >> 1, wn = wid & 1;
    const int cb = blockIdx.x;           // 0..31
    const int rb = blockIdx.y;           // 0..3
    const int row0 = rb * BM;
    const int col0 = cb * BN;

    // ---- load this block's weight slice once (64 KB) ----
    {
        const uint4* src = (const uint4*)g_Wfrag;
        for (int i = tid; i < 4096; i += 256) {
            int q = i & 15, ks = (i >> 4) & 31, j = i >> 9;
            CPA16(smaddr(&Bsm[(ks * 8 + j) * 16 + q]),
                  src + (((size_t)(cb * 8 + j) * 32 + ks) * 16 + q));
        }
        CP_COMMIT; CP_WAIT(0);
    }
    __syncthreads();

    const int arow = wm * 16 + (lane & 15);
    const int acol = (lane & 16) ? 8 : 0;
    float2 Creg[2];                      // cell state, owned per-thread across all t

    for (int t = 0; t < T_; t++) {
        // xproj prefetch (independent of barrier)
        const float* xp = g_xproj + ((size_t)t * B_ + row0) * G4 + col0;
        float4 xv[2][2];
        #pragma unroll
        for (int i = 0; i < 2; i++) {
            int p = tid + i * 256, bi = p >> 3, hp = p & 7;
            xv[i][0] = *(const float4*)(xp + (size_t)bi * G4 + hp * 8);
            xv[i][1] = *(const float4*)(xp + (size_t)bi * G4 + hp * 8 + 4);
        }

        float acc[4][4] = {};
        if (t > 0) {
            // acquire: H[t-1] rows of this rb are complete
            if (tid == 0) {
                volatile unsigned* f = &g_bar[t - 1][rb];
                while (*f < 32u) {}
            }
            __syncthreads();
            __threadfence();

            const __half* Hprev = g_hs + ((size_t)(t - 1) * B_ + row0) * H_;
            // issue all 8 A chunks (64 rows x 64 halfs each)
            #pragma unroll
            for (int kc = 0; kc < 8; kc++) {
                #pragma unroll
                for (int i = 0; i < 2; i++) {
                    int seg = tid + i * 256;          // 512 segs of 16B
                    int r = seg >> 3, q = seg & 7;
                    CPG16(smaddr(Asm + r * 520 + kc * 64 + q * 8),
                          Hprev + (size_t)r * H_ + kc * 64 + q * 8);
                }
                CP_COMMIT;
            }
            #pragma unroll
            for (int kc = 0; kc < 8; kc++) {
                switch (kc) {            // staged waits (compile-time immediates)
                    case 0: CP_WAIT(7); break; case 1: CP_WAIT(6); break;
                    case 2: CP_WAIT(5); break; case 3: CP_WAIT(4); break;
                    case 4: CP_WAIT(3); break; case 5: CP_WAIT(2); break;
                    case 6: CP_WAIT(1); break; default: CP_WAIT(0); break;
                }
                __syncthreads();
                #pragma unroll
                for (int ksl = 0; ksl < 4; ksl++) {
                    int ks = kc * 4 + ksl;
                    unsigned a0, a1, a2, a3;
                    ldmatrix4(a0, a1, a2, a3, smaddr(Asm + arow * 520 + ks * 16 + acol));
                    #pragma unroll
                    for (int j = 0; j < 4; j++) {
                        uint2 b = ((const uint2*)(Bsm + (ks * 8 + wn * 4 + j) * 16))[lane];
                        mma16816(acc[j][0], acc[j][1], acc[j][2], acc[j][3],
                                 a0, a1, a2, a3, b.x, b.y);
                    }
                }
            }
            // dump accum into smem (overlay on A, safe after sync)
            __syncthreads();
            int crow = wm * 16 + (lane >> 2);
            #pragma unroll
            for (int j = 0; j < 4; j++) {
                int c = wn * 32 + j * 8 + (lane & 3) * 2;
                *(float2*)(Csm + crow * 68 + c)       = make_float2(acc[j][0], acc[j][1]);
                *(float2*)(Csm + (crow + 8) * 68 + c) = make_float2(acc[j][2], acc[j][3]);
            }
            __syncthreads();
        }

        // ---- LSTM cell update (C lives in registers) ----
        __half* Hout = g_hs + ((size_t)t * B_ + row0) * H_;
        #pragma unroll
        for (int i = 0; i < 2; i++) {
            int p = tid + i * 256, bi = p >> 3, hp = p & 7;
            float pi0, pf0, po0, pc0, pi1, pf1, po1, pc1;
            if (t > 0) {
                float4 c0 = *(const float4*)(Csm + bi * 68 + hp * 8);
                float4 c1 = *(const float4*)(Csm + bi * 68 + hp * 8 + 4);
                pi0 = c0.x + xv[i][0].x; pf0 = c0.y + xv[i][0].y;
                po0 = c0.z + xv[i][0].z; pc0 = c0.w + xv[i][0].w;
                pi1 = c1.x + xv[i][1].x; pf1 = c1.y + xv[i][1].y;
                po1 = c1.z + xv[i][1].z; pc1 = c1.w + xv[i][1].w;
            } else {
                pi0 = xv[i][0].x; pf0 = xv[i][0].y; po0 = xv[i][0].z; pc0 = xv[i][0].w;
                pi1 = xv[i][1].x; pf1 = xv[i][1].y; po1 = xv[i][1].z; pc1 = xv[i][1].w;
            }
            float I0 = 1.f / (1.f + __expf(-pi0)), F0 = 1.f / (1.f + __expf(-pf0));
            float O0 = 1.f / (1.f + __expf(-po0)), Ch0 = tanhf(pc0);
            float I1 = 1.f / (1.f + __expf(-pi1)), F1 = 1.f / (1.f + __expf(-pf1));
            float O1 = 1.f / (1.f + __expf(-po1)), Ch1 = tanhf(pc1);
            float C0, C1;
            if (t == 0) { C0 = I0 * Ch0; C1 = I1 * Ch1; }
            else {
                C0 = fmaf(F0, Creg[i].x, I0 * Ch0);
                C1 = fmaf(F1, Creg[i].y, I1 * Ch1);
            }
            Creg[i] = make_float2(C0, C1);
            __half2 hv = __floats2half2_rn(O0 * tanhf(C0), O1 * tanhf(C1));
            *(__half2*)(Hout + (size_t)bi * H_ + cb * 16 + hp * 2) = hv;
        }

        // release: post arrival for step t
        __threadfence();
        __syncthreads();
        if (tid == 0) atomicAdd(&g_bar[t][rb], 1u);
    }

    // ---- final barrier + flag cleanup for deterministic graph replay ----
    if (tid == 0) {
        volatile unsigned* f = &g_bar[T_ - 1][rb];
        while (*f < 32u) {}
    }
    __syncthreads();
    if (tid < 16) {                       // this block zeroes its 16-flag slice (t<511)
        int tz = cb * 16 + tid;
        if (tz != T_ - 1) g_bar[tz][rb] = 0;
    }
    if (tid == 0) {
        unsigned prev = atomicAdd(&g_done[rb], 1u);
        if (prev == 31u) {                // last of group: everyone passed final spin
            g_bar[T_ - 1][rb] = 0;
            g_done[rb] = 0;
        }
    }
}

// ---------------- readout: [TB,512] x [512,33] + bias ----------------
__global__ __launch_bounds__(256) void readout_kernel(const float* __restrict__ Wro,
                                                      const float* __restrict__ bro,
                                                      float* __restrict__ out) {
    __shared__ float rows[16][129];
    __shared__ float wsm[128][33];
    int row0 = blockIdx.x * 16;
    int tid = threadIdx.x;
    float acc[3] = {0.f, 0.f, 0.f};
    for (int hc = 0; hc < H_; hc += 128) {
        for (int t2 = tid; t2 < 16 * 128; t2 += 256) {
            int r = t2 >> 7, k = t2 & 127;
            rows[r][k] = __half2float(g_hs[(size_t)(row0 + r) * H_ + hc + k]);
        }
        for (int t2 = tid; t2 < NOUT * 128; t2 += 256) {
            int o = t2 >> 7, k = t2 & 127;
            wsm[k][o] = Wro[o * H_ + hc + k];
        }
        __syncthreads();
        #pragma unroll
        for (int tk = 0; tk < 3; tk++) {
            int idx = tid + tk * 256;
            if (idx < 16 * NOUT) {
                int r = idx / NOUT, o = idx % NOUT;
                float s = 0.f;
                #pragma unroll 8
                for (int k = 0; k < 128; k++) s += rows[r][k] * wsm[k][o];
                acc[tk] += s;
            }
        }
        __syncthreads();
    }
    #pragma unroll
    for (int tk = 0; tk < 3; tk++) {
        int idx = tid + tk * 256;
        if (idx < 16 * NOUT) {
            int r = idx / NOUT, o = idx % NOUT;
            out[(size_t)(row0 + r) * NOUT + o] = acc[tk] + bro[o];
        }
    }
}

// ---------------- launch ----------------
extern "C" void kernel_launch(void* const* d_in, const int* in_sizes, int n_in,
                              void* d_out, int out_size) {
    const float* x   = (const float*)d_in[0];
    const float* Wxi = (const float*)d_in[1];
    const float* Wxf = (const float*)d_in[2];
    const float* Wxo = (const float*)d_in[3];
    const float* Wxc = (const float*)d_in[4];
    const float* Whi = (const float*)d_in[5];
    const float* bhi = (const float*)d_in[6];
    const float* Whf = (const float*)d_in[7];
    const float* bhf = (const float*)d_in[8];
    const float* Who = (const float*)d_in[9];
    const float* bho = (const float*)d_in[10];
    const float* Whc = (const float*)d_in[11];
    const float* bhc = (const float*)d_in[12];
    const float* Wro = (const float*)d_in[13];
    const float* bro = (const float*)d_in[14];
    float* out = (float*)d_out;

    cudaFuncSetAttribute(lstm_persistent,
                         cudaFuncAttributeMaxDynamicSharedMemorySize, SMEM_TOTAL);

    repack_wh_frag<<<(G4/8) * 32 * 32 / 256, 256>>>(Whi, Whf, Who, Whc);
    repack_wx_frag<<<((G4/8) * 6 * 32 + 255) / 256, 256>>>(Wxi, Wxf, Wxo, Wxc);
    pack_bias<<<G4 / 256, 256>>>(bhi, bhf, bho, bhc);
    xcast_kernel<<<(TB * KX + 255) / 256, 256>>>(x);
    xproj_kernel<<<dim3(G4 / 64, TB / 64), 256>>>();
    lstm_persistent<<<dim3(32, 4), 256, SMEM_TOTAL>>>();
    readout_kernel<<<TB / 16, 256>>>(Wro, bro, out);
}

// round 10
// speedup vs baseline: 5.2143x; 1.0200x over previous
#include <cuda_runtime.h>
#include <cuda_fp16.h>
#include <math.h>

#define T_   512
#define B_   256
#define DIN  85
#define H_   512
#define NOUT 33
#define G4   2048          // 4 gates * H, interleaved n = h*4+g (g: 0=i,1=f,2=o,3=c)
#define TB   (T_*B_)
#define KX   96            // DIN padded to multiple of 16
#define BM   64
#define BN   64

// ---------------- scratch (device globals) ----------------
__device__ float  g_xproj[(size_t)TB * G4];            // x-side preacts + bias (fp32)
__device__ __half g_hs[(size_t)TB * H_];               // hidden states fp16
__device__ uint2  g_Wfrag[(G4/8) * (H_/16) * 32];      // recurrent W frags [n8][ks][lane]
__device__ uint2  g_WxFrag[(G4/8) * (KX/16) * 32];     // input W frags [n8][ks(6)][lane]
__device__ float  g_bias4[G4];                         // packed biases per n
__device__ unsigned g_flag[T_ * 4 * 32 * 32];          // per (t,rb,producer) flag, 128B stride
__device__ unsigned g_done[4];                         // end-of-run phase-1 counters
__device__ unsigned g_done2[4];                        // end-of-run phase-2 counters

#define FIDX(t, rb, cb) ((((t) * 4 + (rb)) * 32 + (cb)) * 32)

// ---------------- helpers ----------------
__device__ __forceinline__ unsigned smaddr(const void* p) {
    return (unsigned)__cvta_generic_to_shared(p);
}
#define CPG16(dst, src) asm volatile("cp.async.cg.shared.global [%0], [%1], 16;\n" :: "r"(dst), "l"(src))
#define CPA16(dst, src) asm volatile("cp.async.ca.shared.global [%0], [%1], 16;\n" :: "r"(dst), "l"(src))
#define CP_COMMIT       asm volatile("cp.async.commit_group;\n")
#define CP_WAIT(N)      asm volatile("cp.async.wait_group %0;\n" :: "n"(N))

__device__ __forceinline__ void mma16816(float& d0, float& d1, float& d2, float& d3,
                                         unsigned a0, unsigned a1, unsigned a2, unsigned a3,
                                         unsigned b0, unsigned b1) {
    asm volatile("mma.sync.aligned.m16n8k16.row.col.f32.f16.f16.f32 "
                 "{%0,%1,%2,%3}, {%4,%5,%6,%7}, {%8,%9}, {%0,%1,%2,%3};\n"
                 : "+f"(d0), "+f"(d1), "+f"(d2), "+f"(d3)
                 : "r"(a0), "r"(a1), "r"(a2), "r"(a3), "r"(b0), "r"(b1));
}
__device__ __forceinline__ void ldmatrix4(unsigned& r0, unsigned& r1, unsigned& r2, unsigned& r3,
                                          unsigned addr) {
    asm volatile("ldmatrix.sync.aligned.m8n8.x4.shared.b16 {%0,%1,%2,%3}, [%4];\n"
                 : "=r"(r0), "=r"(r1), "=r"(r2), "=r"(r3) : "r"(addr));
}
__device__ __forceinline__ unsigned packh2(float a, float b) {
    __half2 h = __floats2half2_rn(a, b);
    return *reinterpret_cast<unsigned*>(&h);
}
__device__ __forceinline__ unsigned ld_acq(const unsigned* p) {
    unsigned v;
    asm volatile("ld.global.acquire.gpu.u32 %0, [%1];" : "=r"(v) : "l"(p));
    return v;
}
__device__ __forceinline__ void st_rel(unsigned* p, unsigned v) {
    asm volatile("st.global.release.gpu.u32 [%0], %1;" :: "l"(p), "r"(v));
}
__device__ __forceinline__ float fsigm(float x) {   // fast sigmoid
    return __fdividef(1.f, 1.f + __expf(-x));
}
__device__ __forceinline__ float ftanh(float x) {   // fast tanh: 1 - 2/(e^2x+1)
    return 1.f - __fdividef(2.f, __expf(2.f * x) + 1.f);
}

// ---------------- weight repack into B-fragment layout ----------------
__global__ void repack_wh_frag(const float* __restrict__ Whi, const float* __restrict__ Whf,
                               const float* __restrict__ Who, const float* __restrict__ Whc) {
    int idx = blockIdx.x * blockDim.x + threadIdx.x;
    if (idx >= (G4/8) * 32 * 32) return;
    int lane = idx & 31, ks = (idx >> 5) & 31, n8 = idx >> 10;
    int n = n8 * 8 + (lane >> 2), h = n >> 2, g = n & 3;
    int k0 = ks * 16 + (lane & 3) * 2;
    const float* W = (g == 0) ? Whi : (g == 1) ? Whf : (g == 2) ? Who : Whc;
    const float* Wr = W + (size_t)h * H_;
    uint2 v;
    v.x = packh2(Wr[k0],     Wr[k0 + 1]);
    v.y = packh2(Wr[k0 + 8], Wr[k0 + 9]);
    g_Wfrag[idx] = v;
}
__global__ void repack_wx_frag(const float* __restrict__ Wxi, const float* __restrict__ Wxf,
                               const float* __restrict__ Wxo, const float* __restrict__ Wxc) {
    int idx = blockIdx.x * blockDim.x + threadIdx.x;
    if (idx >= (G4/8) * 6 * 32) return;
    int lane = idx & 31, ks = (idx >> 5) % 6, n8 = idx / 192;
    int n = n8 * 8 + (lane >> 2), h = n >> 2, g = n & 3;
    int k0 = ks * 16 + (lane & 3) * 2;
    const float* W = (g == 0) ? Wxi : (g == 1) ? Wxf : (g == 2) ? Wxo : Wxc;
    const float* Wr = W + (size_t)h * DIN;
    float e0 = (k0     < DIN) ? Wr[k0]     : 0.f;
    float e1 = (k0 + 1 < DIN) ? Wr[k0 + 1] : 0.f;
    float e2 = (k0 + 8 < DIN) ? Wr[k0 + 8] : 0.f;
    float e3 = (k0 + 9 < DIN) ? Wr[k0 + 9] : 0.f;
    uint2 v; v.x = packh2(e0, e1); v.y = packh2(e2, e3);
    g_WxFrag[idx] = v;
}
__global__ void pack_bias(const float* __restrict__ bhi, const float* __restrict__ bhf,
                          const float* __restrict__ bho, const float* __restrict__ bhc) {
    int n = blockIdx.x * blockDim.x + threadIdx.x;
    if (n >= G4) return;
    int h = n >> 2, g = n & 3;
    g_bias4[n] = (g == 0) ? bhi[h] : (g == 1) ? bhf[h] : (g == 2) ? bho[h] : bhc[h];
}

// ---------------- x projection via mma (fused fp32->fp16 cast) ----------------
__global__ __launch_bounds__(256) void xproj_kernel(const float* __restrict__ x) {
    __shared__ __half As[64][104];
    int row0 = blockIdx.y * 64;
    int col0 = blockIdx.x * 64;
    int tid = threadIdx.x, lane = tid & 31, wid = tid >> 5;
    int wm = wid >> 1, wn = wid & 1;

    for (int i = tid; i < 64 * KX; i += 256) {
        int r = i / KX, k = i % KX;
        float v = (k < DIN) ? x[(size_t)(row0 + r) * DIN + k] : 0.f;
        As[r][k] = __float2half_rn(v);
    }
    __syncthreads();

    float acc[4][4] = {};
    int arow = wm * 16 + (lane & 15);
    int acol = (lane & 16) ? 8 : 0;
    int n8base = blockIdx.x * 8 + wn * 4;
    #pragma unroll
    for (int ks = 0; ks < 6; ks++) {
        unsigned a0, a1, a2, a3;
        ldmatrix4(a0, a1, a2, a3, smaddr(&As[arow][ks * 16 + acol]));
        #pragma unroll
        for (int j = 0; j < 4; j++) {
            uint2 b = g_WxFrag[((n8base + j) * 6 + ks) * 32 + lane];
            mma16816(acc[j][0], acc[j][1], acc[j][2], acc[j][3], a0, a1, a2, a3, b.x, b.y);
        }
    }
    int r0 = row0 + wm * 16 + (lane >> 2);
    #pragma unroll
    for (int j = 0; j < 4; j++) {
        int n = col0 + wn * 32 + j * 8 + (lane & 3) * 2;
        float bx = g_bias4[n], by = g_bias4[n + 1];
        *(float2*)&g_xproj[(size_t)r0 * G4 + n]       = make_float2(acc[j][0] + bx, acc[j][1] + by);
        *(float2*)&g_xproj[(size_t)(r0 + 8) * G4 + n] = make_float2(acc[j][2] + bx, acc[j][3] + by);
    }
}

// ---------------- persistent recurrence kernel ----------------
// grid (32, 4): 128 blocks, 1/SM. Block (rb,cb): batch rows [rb*64,+64),
// n cols [cb*64,+64) == h [cb*16,+16). Weights resident in smem for all T.
// Sync: per-producer release flags (128B apart), warp0 ballot-poll acquire.
#define SMEM_B_BYTES 65536                       // 8 n8frags x 32 ks x 256B
#define SMEM_A_BYTES (64 * 520 * 2)              // A tile 64x512 halfs, +8 pad/row
#define SMEM_TOTAL   (SMEM_B_BYTES + SMEM_A_BYTES)

__global__ __launch_bounds__(256, 1) void lstm_persistent() {
    extern __shared__ char smraw[];
    uint4*  Bsm = (uint4*)smraw;                       // [ (ks*8+j)*16 + q ]
    __half* Asm = (__half*)(smraw + SMEM_B_BYTES);     // [64][520]

    const int tid = threadIdx.x, lane = tid & 31, wid = tid >> 5;
    const int wm = wid >> 1, wn = wid & 1;
    const int cb = blockIdx.x;           // 0..31
    const int rb = blockIdx.y;           // 0..3
    const int row0 = rb * BM;
    const int col0 = cb * BN;

    // ---- load this block's weight slice once (64 KB) ----
    {
        const uint4* src = (const uint4*)g_Wfrag;
        for (int i = tid; i < 4096; i += 256) {
            int q = i & 15, ks = (i >> 4) & 31, j = i >> 9;
            CPA16(smaddr(&Bsm[(ks * 8 + j) * 16 + q]),
                  src + (((size_t)(cb * 8 + j) * 32 + ks) * 16 + q));
        }
        CP_COMMIT; CP_WAIT(0);
    }
    __syncthreads();

    const int arow = wm * 16 + (lane & 15);
    const int acol = (lane & 16) ? 8 : 0;
    const int odd  = lane & 1;
    const int hsel = (lane >> 1) & 1;
    const int lrow = wm * 16 + (lane >> 2) + odd * 8;    // local batch row 0..63
    float Creg[4];                       // cell state (one h per j), fixed per-thread for all t

    for (int t = 0; t < T_; t++) {
        // xproj prefetch (independent of cross-block sync; overlaps the poll)
        const float* xp = g_xproj + ((size_t)t * B_ + row0 + lrow) * G4 + col0;
        float4 xv[4];
        #pragma unroll
        for (int j = 0; j < 4; j++)
            xv[j] = *(const float4*)(xp + (wn * 8 + j * 2 + hsel) * 4);

        float acc[4][4] = {};
        if (t > 0) {
            // acquire: all 32 producers of this rb finished step t-1
            if (wid == 0) {
                const unsigned* fp = &g_flag[FIDX(t - 1, rb, lane)];
                while (__ballot_sync(0xffffffffu, ld_acq(fp) == 0u)) {}
            }
            __syncthreads();

            const __half* Hprev = g_hs + ((size_t)(t - 1) * B_ + row0) * H_;
            #pragma unroll
            for (int kc = 0; kc < 8; kc++) {           // issue all 8 A chunks
                #pragma unroll
                for (int i = 0; i < 2; i++) {
                    int seg = tid + i * 256;           // 512 segs of 16B per chunk
                    int r = seg >> 3, q = seg & 7;
                    CPG16(smaddr(Asm + r * 520 + kc * 64 + q * 8),
                          Hprev + (size_t)r * H_ + kc * 64 + q * 8);
                }
                CP_COMMIT;
            }
            #pragma unroll
            for (int kc = 0; kc < 8; kc++) {
                switch (kc) {
                    case 0: CP_WAIT(7); break; case 1: CP_WAIT(6); break;
                    case 2: CP_WAIT(5); break; case 3: CP_WAIT(4); break;
                    case 4: CP_WAIT(3); break; case 5: CP_WAIT(2); break;
                    case 6: CP_WAIT(1); break; default: CP_WAIT(0); break;
                }
                __syncthreads();
                #pragma unroll
                for (int ksl = 0; ksl < 4; ksl++) {
                    int ks = kc * 4 + ksl;
                    unsigned a0, a1, a2, a3;
                    ldmatrix4(a0, a1, a2, a3, smaddr(Asm + arow * 520 + ks * 16 + acol));
                    #pragma unroll
                    for (int j = 0; j < 4; j++) {
                        uint2 b = ((const uint2*)(Bsm + (ks * 8 + wn * 4 + j) * 16))[lane];
                        mma16816(acc[j][0], acc[j][1], acc[j][2], acc[j][3],
                                 a0, a1, a2, a3, b.x, b.y);
                    }
                }
            }
        }

        // ---- epilogue: shfl gate exchange, C in registers, no smem round trip ----
        __half* Hrow = g_hs + ((size_t)t * B_ + row0 + lrow) * H_ + cb * 16;
        #pragma unroll
        for (int j = 0; j < 4; j++) {
            float s0 = odd ? acc[j][0] : acc[j][2];
            float s1 = odd ? acc[j][1] : acc[j][3];
            float r0 = __shfl_xor_sync(0xffffffffu, s0, 1);
            float r1 = __shfl_xor_sync(0xffffffffu, s1, 1);
            float o0 = odd ? acc[j][2] : acc[j][0];
            float o1 = odd ? acc[j][3] : acc[j][1];
            float pi = (odd ? r0 : o0) + xv[j].x;
            float pf = (odd ? r1 : o1) + xv[j].y;
            float po = (odd ? o0 : r0) + xv[j].z;
            float pc = (odd ? o1 : r1) + xv[j].w;
            float I = fsigm(pi), F = fsigm(pf), O = fsigm(po), Ch = ftanh(pc);
            float C = (t == 0) ? (I * Ch) : fmaf(F, Creg[j], I * Ch);
            Creg[j] = C;
            Hrow[wn * 8 + j * 2 + hsel] = __float2half_rn(O * ftanh(C));
        }

        // release: publish this block's H tile for step t
        if (t < T_ - 1) {
            __threadfence();
            __syncthreads();
            if (tid == 0) st_rel(&g_flag[FIDX(t, rb, cb)], 1u);
        }
    }

    // ---- end-of-run: two-phase cleanup so graph replays see zeroed flags ----
    __threadfence();
    if (tid == 0) {
        atomicAdd(&g_done[rb], 1u);
        volatile unsigned* d = &g_done[rb];
        while (*d < 32u) {}
    }
    __syncthreads();
    for (int tz = tid; tz < T_ - 1; tz += 256)
        g_flag[FIDX(tz, rb, cb)] = 0;
    __threadfence();
    __syncthreads();
    if (tid == 0) {
        unsigned prev = atomicAdd(&g_done2[rb], 1u);
        if (prev == 31u) {            // last block: everyone finished zeroing
            g_done[rb] = 0;
            g_done2[rb] = 0;
            __threadfence();
        }
    }
}

// ---------------- readout: [TB,512] x [512,33] + bias ----------------
__global__ __launch_bounds__(256) void readout_kernel(const float* __restrict__ Wro,
                                                      const float* __restrict__ bro,
                                                      float* __restrict__ out) {
    __shared__ float rows[16][129];
    __shared__ float wsm[128][33];
    int row0 = blockIdx.x * 16;
    int tid = threadIdx.x;
    float acc[3] = {0.f, 0.f, 0.f};
    for (int hc = 0; hc < H_; hc += 128) {
        for (int t2 = tid; t2 < 16 * 128; t2 += 256) {
            int r = t2 >> 7, k = t2 & 127;
            rows[r][k] = __half2float(g_hs[(size_t)(row0 + r) * H_ + hc + k]);
        }
        for (int t2 = tid; t2 < NOUT * 128; t2 += 256) {
            int o = t2 >> 7, k = t2 & 127;
            wsm[k][o] = Wro[o * H_ + hc + k];
        }
        __syncthreads();
        #pragma unroll
        for (int tk = 0; tk < 3; tk++) {
            int idx = tid + tk * 256;
            if (idx < 16 * NOUT) {
                int r = idx / NOUT, o = idx % NOUT;
                float s = 0.f;
                #pragma unroll 8
                for (int k = 0; k < 128; k++) s += rows[r][k] * wsm[k][o];
                acc[tk] += s;
            }
        }
        __syncthreads();
    }
    #pragma unroll
    for (int tk = 0; tk < 3; tk++) {
        int idx = tid + tk * 256;
        if (idx < 16 * NOUT) {
            int r = idx / NOUT, o = idx % NOUT;
            out[(size_t)(row0 + r) * NOUT + o] = acc[tk] + bro[o];
        }
    }
}

// ---------------- launch ----------------
extern "C" void kernel_launch(void* const* d_in, const int* in_sizes, int n_in,
                              void* d_out, int out_size) {
    const float* x   = (const float*)d_in[0];
    const float* Wxi = (const float*)d_in[1];
    const float* Wxf = (const float*)d_in[2];
    const float* Wxo = (const float*)d_in[3];
    const float* Wxc = (const float*)d_in[4];
    const float* Whi = (const float*)d_in[5];
    const float* bhi = (const float*)d_in[6];
    const float* Whf = (const float*)d_in[7];
    const float* bhf = (const float*)d_in[8];
    const float* Who = (const float*)d_in[9];
    const float* bho = (const float*)d_in[10];
    const float* Whc = (const float*)d_in[11];
    const float* bhc = (const float*)d_in[12];
    const float* Wro = (const float*)d_in[13];
    const float* bro = (const float*)d_in[14];
    float* out = (float*)d_out;

    cudaFuncSetAttribute(lstm_persistent,
                         cudaFuncAttributeMaxDynamicSharedMemorySize, SMEM_TOTAL);

    repack_wh_frag<<<(G4/8) * 32 * 32 / 256, 256>>>(Whi, Whf, Who, Whc);
    repack_wx_frag<<<((G4/8) * 6 * 32 + 255) / 256, 256>>>(Wxi, Wxf, Wxo, Wxc);
    pack_bias<<<G4 / 256, 256>>>(bhi, bhf, bho, bhc);
    xproj_kernel<<<dim3(G4 / 64, TB / 64), 256>>>(x);
    lstm_persistent<<<dim3(32, 4), 256, SMEM_TOTAL>>>();
    readout_kernel<<<TB / 16, 256>>>(Wro, bro, out);
}

// round 11
// speedup vs baseline: 6.1855x; 1.1862x over previous
#include <cuda_runtime.h>
#include <cuda_fp16.h>
#include <math.h>

#define T_   512
#define B_   256
#define DIN  85
#define H_   512
#define NOUT 33
#define G4   2048          // 4 gates * H, interleaved n = h*4+g (g: 0=i,1=f,2=o,3=c)
#define TB   (T_*B_)
#define KXH  96            // DIN padded to multiple of 16
#define BM   64
#define BN   64

// ---------------- scratch (device globals) ----------------
__device__ __half g_hs[(size_t)TB * H_];               // hidden states fp16
__device__ __half g_xh[(size_t)TB * KXH];              // x cast to fp16, K padded
__device__ uint2  g_Wfrag[(G4/8) * (H_/16) * 32];      // recurrent W frags [n8][ks][lane]
__device__ uint2  g_WxFrag[(G4/8) * (KXH/16) * 32];    // input W frags [n8][ks(6)][lane]
__device__ float  g_bias4[G4];                         // packed biases per n
__device__ unsigned g_flag[T_ * 4 * 32 * 32];          // per (t,rb,producer) flag, 128B stride
__device__ unsigned g_done[4];                         // end-of-run phase-1 counters
__device__ unsigned g_done2[4];                        // end-of-run phase-2 counters

#define FIDX(t, rb, cb) ((((t) * 4 + (rb)) * 32 + (cb)) * 32)

// ---------------- helpers ----------------
__device__ __forceinline__ unsigned smaddr(const void* p) {
    return (unsigned)__cvta_generic_to_shared(p);
}
#define CPG16(dst, src) asm volatile("cp.async.cg.shared.global [%0], [%1], 16;\n" :: "r"(dst), "l"(src))
#define CPA16(dst, src) asm volatile("cp.async.ca.shared.global [%0], [%1], 16;\n" :: "r"(dst), "l"(src))
#define CP_COMMIT       asm volatile("cp.async.commit_group;\n")
#define CP_WAIT(N)      asm volatile("cp.async.wait_group %0;\n" :: "n"(N))

__device__ __forceinline__ void mma16816(float& d0, float& d1, float& d2, float& d3,
                                         unsigned a0, unsigned a1, unsigned a2, unsigned a3,
                                         unsigned b0, unsigned b1) {
    asm volatile("mma.sync.aligned.m16n8k16.row.col.f32.f16.f16.f32 "
                 "{%0,%1,%2,%3}, {%4,%5,%6,%7}, {%8,%9}, {%0,%1,%2,%3};\n"
                 : "+f"(d0), "+f"(d1), "+f"(d2), "+f"(d3)
                 : "r"(a0), "r"(a1), "r"(a2), "r"(a3), "r"(b0), "r"(b1));
}
__device__ __forceinline__ void ldmatrix4(unsigned& r0, unsigned& r1, unsigned& r2, unsigned& r3,
                                          unsigned addr) {
    asm volatile("ldmatrix.sync.aligned.m8n8.x4.shared.b16 {%0,%1,%2,%3}, [%4];\n"
                 : "=r"(r0), "=r"(r1), "=r"(r2), "=r"(r3) : "r"(addr));
}
__device__ __forceinline__ unsigned packh2(float a, float b) {
    __half2 h = __floats2half2_rn(a, b);
    return *reinterpret_cast<unsigned*>(&h);
}
__device__ __forceinline__ unsigned ld_acq(const unsigned* p) {
    unsigned v;
    asm volatile("ld.global.acquire.gpu.u32 %0, [%1];" : "=r"(v) : "l"(p));
    return v;
}
__device__ __forceinline__ void st_rel(unsigned* p, unsigned v) {
    asm volatile("st.global.release.gpu.u32 [%0], %1;" :: "l"(p), "r"(v));
}
__device__ __forceinline__ float fsigm(float x) {
    return __fdividef(1.f, 1.f + __expf(-x));
}
__device__ __forceinline__ float ftanh(float x) {
    return 1.f - __fdividef(2.f, __expf(2.f * x) + 1.f);
}

// ---------------- weight repack into B-fragment layout ----------------
__global__ void repack_wh_frag(const float* __restrict__ Whi, const float* __restrict__ Whf,
                               const float* __restrict__ Who, const float* __restrict__ Whc) {
    int idx = blockIdx.x * blockDim.x + threadIdx.x;
    if (idx >= (G4/8) * 32 * 32) return;
    int lane = idx & 31, ks = (idx >> 5) & 31, n8 = idx >> 10;
    int n = n8 * 8 + (lane >> 2), h = n >> 2, g = n & 3;
    int k0 = ks * 16 + (lane & 3) * 2;
    const float* W = (g == 0) ? Whi : (g == 1) ? Whf : (g == 2) ? Who : Whc;
    const float* Wr = W + (size_t)h * H_;
    uint2 v;
    v.x = packh2(Wr[k0],     Wr[k0 + 1]);
    v.y = packh2(Wr[k0 + 8], Wr[k0 + 9]);
    g_Wfrag[idx] = v;
}
__global__ void repack_wx_frag(const float* __restrict__ Wxi, const float* __restrict__ Wxf,
                               const float* __restrict__ Wxo, const float* __restrict__ Wxc) {
    int idx = blockIdx.x * blockDim.x + threadIdx.x;
    if (idx >= (G4/8) * 6 * 32) return;
    int lane = idx & 31, ks = (idx >> 5) % 6, n8 = idx / 192;
    int n = n8 * 8 + (lane >> 2), h = n >> 2, g = n & 3;
    int k0 = ks * 16 + (lane & 3) * 2;
    const float* W = (g == 0) ? Wxi : (g == 1) ? Wxf : (g == 2) ? Wxo : Wxc;
    const float* Wr = W + (size_t)h * DIN;
    float e0 = (k0     < DIN) ? Wr[k0]     : 0.f;
    float e1 = (k0 + 1 < DIN) ? Wr[k0 + 1] : 0.f;
    float e2 = (k0 + 8 < DIN) ? Wr[k0 + 8] : 0.f;
    float e3 = (k0 + 9 < DIN) ? Wr[k0 + 9] : 0.f;
    uint2 v; v.x = packh2(e0, e1); v.y = packh2(e2, e3);
    g_WxFrag[idx] = v;
}
__global__ void pack_bias(const float* __restrict__ bhi, const float* __restrict__ bhf,
                          const float* __restrict__ bho, const float* __restrict__ bhc) {
    int n = blockIdx.x * blockDim.x + threadIdx.x;
    if (n >= G4) return;
    int h = n >> 2, g = n & 3;
    g_bias4[n] = (g == 0) ? bhi[h] : (g == 1) ? bhf[h] : (g == 2) ? bho[h] : bhc[h];
}
__global__ void xcast_kernel(const float* __restrict__ x) {
    int idx = blockIdx.x * blockDim.x + threadIdx.x;
    if (idx >= TB * KXH) return;
    int row = idx / KXH, col = idx - row * KXH;
    g_xh[idx] = __float2half_rn((col < DIN) ? x[(size_t)row * DIN + col] : 0.f);
}

// ---------------- persistent kernel: xproj + recurrence fused ----------------
// grid (32, 4): 128 blocks, 1/SM. Block (rb,cb): batch rows [rb*64,+64),
// n cols [cb*64,+64) == h [cb*16,+16).
// Per step: x-side mma (6 ksteps, smem-prefetched) hidden under the flag poll,
// then recurrent mma over H[t-1] in 4 cp.async chunks, register cell update.
#define OFF_B   0                                  // 65536 B : recurrent W frags
#define OFF_BX  65536                              // 12288 B : input W frags
#define OFF_A   77824                              // 66560 B : A tile 64x520 halfs
#define OFF_X   144384                             // 2x13312 B: x tiles 64x104 halfs
#define XBUFB   13312
#define SMEM_TOTAL 171008

__global__ __launch_bounds__(256, 1) void lstm_persistent() {
    extern __shared__ char smraw[];
    uint4*  Bsm  = (uint4*)(smraw + OFF_B);
    uint4*  BXsm = (uint4*)(smraw + OFF_BX);
    __half* Asm  = (__half*)(smraw + OFF_A);

    const int tid = threadIdx.x, lane = tid & 31, wid = tid >> 5;
    const int wm = wid >> 1, wn = wid & 1;
    const int cb = blockIdx.x;           // 0..31
    const int rb = blockIdx.y;           // 0..3
    const int row0 = rb * BM;

    // ---- resident weight slices + X(t=0) tile ----
    {
        const uint4* src = (const uint4*)g_Wfrag;
        for (int i = tid; i < 4096; i += 256) {
            int q = i & 15, ks = (i >> 4) & 31, j = i >> 9;
            CPA16(smaddr(&Bsm[(ks * 8 + j) * 16 + q]),
                  src + (((size_t)(cb * 8 + j) * 32 + ks) * 16 + q));
        }
        const uint4* srcx = (const uint4*)g_WxFrag;
        for (int i = tid; i < 768; i += 256) {
            int q = i & 15, f = i >> 4, j = f & 7, ks = f >> 3;
            CPA16(smaddr(&BXsm[(ks * 8 + j) * 16 + q]),
                  srcx + (((size_t)(cb * 8 + j) * 6 + ks) * 16 + q));
        }
        for (int i = tid; i < 768; i += 256) {
            int r = i / 12, q = i - r * 12;
            CPA16(smaddr(smraw + OFF_X) + (r * 104 + q * 8) * 2,
                  g_xh + ((size_t)row0 + r) * KXH + q * 8);
        }
        CP_COMMIT; CP_WAIT(0);
    }
    __syncthreads();

    // ---- per-thread precomputed offsets ----
    int aoff[4]; unsigned adst[4];
    #pragma unroll
    for (int i = 0; i < 4; i++) {
        int s = tid + i * 256, r = s >> 4, q = s & 15;
        aoff[i] = r * H_ + q * 8;
        adst[i] = smaddr(Asm) + (r * 520 + q * 8) * 2;
    }
    int xoff[3]; unsigned xdst[3];
    #pragma unroll
    for (int i = 0; i < 3; i++) {
        int s = tid + i * 256, r = s / 12, q = s - r * 12;
        xoff[i] = (row0 + r) * KXH + q * 8;
        xdst[i] = smaddr(smraw + OFF_X) + (r * 104 + q * 8) * 2;
    }
    const int arow = wm * 16 + (lane & 15);
    const int acol = (lane & 16) ? 8 : 0;
    const int odd  = lane & 1;
    const int hsel = (lane >> 1) & 1;
    const int lrow = wm * 16 + (lane >> 2) + odd * 8;
    float4 biasv[4];
    #pragma unroll
    for (int j = 0; j < 4; j++)
        biasv[j] = *(const float4*)&g_bias4[cb * BN + (wn * 8 + j * 2 + hsel) * 4];
    const uint2* Bl  = (const uint2*)Bsm  + lane;
    const uint2* BXl = (const uint2*)BXsm + lane;
    const unsigned xbase = smaddr(smraw + OFF_X);
    const unsigned abase = smaddr(Asm);
    float Creg[4];
    int buf = 0;

    for (int t = 0; t < T_; t++) {
        float acc[4][4] = {};
        if (t > 0 && wid == 0) {             // poll 32 producers of this rb
            const unsigned* fp = &g_flag[FIDX(t - 1, rb, lane)];
            while (__ballot_sync(0xffffffffu, ld_acq(fp) == 0u)) {}
        }
        // x-side mma: barrier-independent, overlaps warp0's poll
        {
            unsigned xb = xbase + buf * XBUFB;
            #pragma unroll
            for (int ks = 0; ks < 6; ks++) {
                unsigned a0, a1, a2, a3;
                ldmatrix4(a0, a1, a2, a3, xb + (arow * 104 + ks * 16 + acol) * 2);
                #pragma unroll
                for (int j = 0; j < 4; j++) {
                    uint2 b = BXl[(ks * 8 + wn * 4 + j) * 32];
                    mma16816(acc[j][0], acc[j][1], acc[j][2], acc[j][3],
                             a0, a1, a2, a3, b.x, b.y);
                }
            }
        }
        __syncthreads();                     // joins poll result

        if (t > 0) {
            if (t + 1 < T_) {                // prefetch X(t+1) (group X)
                const __half* xs = g_xh + (size_t)(t + 1) * B_ * KXH;
                #pragma unroll
                for (int i = 0; i < 3; i++)
                    CPG16(xdst[i] + (buf ^ 1) * XBUFB, xs + xoff[i]);
                CP_COMMIT;
            }
            const __half* Hp = g_hs + ((size_t)(t - 1) * B_ + row0) * H_;
            #pragma unroll
            for (int kc = 0; kc < 4; kc++) { // groups C0..C3
                #pragma unroll
                for (int i = 0; i < 4; i++)
                    CPG16(adst[i] + kc * 256, Hp + aoff[i] + kc * 128);
                CP_COMMIT;
            }
            #pragma unroll
            for (int kc = 0; kc < 4; kc++) {
                switch (kc) { case 0: CP_WAIT(3); break; case 1: CP_WAIT(2); break;
                              case 2: CP_WAIT(1); break; default: CP_WAIT(0); break; }
                __syncthreads();
                #pragma unroll
                for (int ksl = 0; ksl < 8; ksl++) {
                    int ks = kc * 8 + ksl;
                    unsigned a0, a1, a2, a3;
                    ldmatrix4(a0, a1, a2, a3, abase + (arow * 520 + ks * 16 + acol) * 2);
                    #pragma unroll
                    for (int j = 0; j < 4; j++) {
                        uint2 b = Bl[(ks * 8 + wn * 4 + j) * 32];
                        mma16816(acc[j][0], acc[j][1], acc[j][2], acc[j][3],
                                 a0, a1, a2, a3, b.x, b.y);
                    }
                }
            }
        } else {
            // t==0: prefetch X(1) and fully wait (no chunk waits this step)
            const __half* xs = g_xh + (size_t)B_ * KXH;
            #pragma unroll
            for (int i = 0; i < 3; i++)
                CPG16(xdst[i] + XBUFB, xs + xoff[i]);
            CP_COMMIT; CP_WAIT(0);
            __syncthreads();
        }

        // ---- epilogue: gate shfl exchange, C in regs, vectorized H publish ----
        __half* Hrow = g_hs + ((size_t)t * B_ + row0 + lrow) * H_ + cb * 16;
        unsigned hb[4];
        #pragma unroll
        for (int j = 0; j < 4; j++) {
            float s0 = odd ? acc[j][0] : acc[j][2];
            float s1 = odd ? acc[j][1] : acc[j][3];
            float r0 = __shfl_xor_sync(0xffffffffu, s0, 1);
            float r1 = __shfl_xor_sync(0xffffffffu, s1, 1);
            float o0 = odd ? acc[j][2] : acc[j][0];
            float o1 = odd ? acc[j][3] : acc[j][1];
            float pi = (odd ? r0 : o0) + biasv[j].x;
            float pf = (odd ? r1 : o1) + biasv[j].y;
            float po = (odd ? o0 : r0) + biasv[j].z;
            float pc = (odd ? o1 : r1) + biasv[j].w;
            float I = fsigm(pi), F = fsigm(pf), O = fsigm(po), Ch = ftanh(pc);
            float C = (t == 0) ? (I * Ch) : fmaf(F, Creg[j], I * Ch);
            Creg[j] = C;
            hb[j] = (unsigned)__half_as_ushort(__float2half_rn(O * ftanh(C)));
        }
        unsigned pb0 = __shfl_xor_sync(0xffffffffu, hb[0], 2);
        unsigned pb1 = __shfl_xor_sync(0xffffffffu, hb[1], 2);
        unsigned pb2 = __shfl_xor_sync(0xffffffffu, hb[2], 2);
        unsigned pb3 = __shfl_xor_sync(0xffffffffu, hb[3], 2);
        if (hsel == 0) {                     // one STG.128 covers 8 halfs of the row
            uint4 v;
            v.x = hb[0] | (pb0 << 16);
            v.y = hb[1] | (pb1 << 16);
            v.z = hb[2] | (pb2 << 16);
            v.w = hb[3] | (pb3 << 16);
            *(uint4*)&Hrow[wn * 8] = v;
        }

        // release: bar (cta-wide ordering) + single-thread gpu fence + flag
        if (t < T_ - 1) {
            __syncthreads();
            if (tid == 0) {
                asm volatile("fence.acq_rel.gpu;" ::: "memory");
                st_rel(&g_flag[FIDX(t, rb, cb)], 1u);
            }
        }
        buf ^= 1;
    }

    // ---- end-of-run: two-phase cleanup so graph replays see zeroed flags ----
    __threadfence();
    if (tid == 0) {
        atomicAdd(&g_done[rb], 1u);
        volatile unsigned* d = &g_done[rb];
        while (*d < 32u) {}
    }
    __syncthreads();
    for (int tz = tid; tz < T_ - 1; tz += 256)
        g_flag[FIDX(tz, rb, cb)] = 0;
    __threadfence();
    __syncthreads();
    if (tid == 0) {
        unsigned prev = atomicAdd(&g_done2[rb], 1u);
        if (prev == 31u) {
            g_done[rb] = 0;
            g_done2[rb] = 0;
            __threadfence();
        }
    }
}

// ---------------- readout: [TB,512] x [512,33] + bias ----------------
__global__ __launch_bounds__(256) void readout_kernel(const float* __restrict__ Wro,
                                                      const float* __restrict__ bro,
                                                      float* __restrict__ out) {
    __shared__ float rows[16][129];
    __shared__ float wsm[128][33];
    int row0 = blockIdx.x * 16;
    int tid = threadIdx.x;
    float acc[3] = {0.f, 0.f, 0.f};
    for (int hc = 0; hc < H_; hc += 128) {
        for (int t2 = tid; t2 < 16 * 128; t2 += 256) {
            int r = t2 >> 7, k = t2 & 127;
            rows[r][k] = __half2float(g_hs[(size_t)(row0 + r) * H_ + hc + k]);
        }
        for (int t2 = tid; t2 < NOUT * 128; t2 += 256) {
            int o = t2 >> 7, k = t2 & 127;
            wsm[k][o] = Wro[o * H_ + hc + k];
        }
        __syncthreads();
        #pragma unroll
        for (int tk = 0; tk < 3; tk++) {
            int idx = tid + tk * 256;
            if (idx < 16 * NOUT) {
                int r = idx / NOUT, o = idx % NOUT;
                float s = 0.f;
                #pragma unroll 8
                for (int k = 0; k < 128; k++) s += rows[r][k] * wsm[k][o];
                acc[tk] += s;
            }
        }
        __syncthreads();
    }
    #pragma unroll
    for (int tk = 0; tk < 3; tk++) {
        int idx = tid + tk * 256;
        if (idx < 16 * NOUT) {
            int r = idx / NOUT, o = idx % NOUT;
            out[(size_t)(row0 + r) * NOUT + o] = acc[tk] + bro[o];
        }
    }
}

// ---------------- launch ----------------
extern "C" void kernel_launch(void* const* d_in, const int* in_sizes, int n_in,
                              void* d_out, int out_size) {
    const float* x   = (const float*)d_in[0];
    const float* Wxi = (const float*)d_in[1];
    const float* Wxf = (const float*)d_in[2];
    const float* Wxo = (const float*)d_in[3];
    const float* Wxc = (const float*)d_in[4];
    const float* Whi = (const float*)d_in[5];
    const float* bhi = (const float*)d_in[6];
    const float* Whf = (const float*)d_in[7];
    const float* bhf = (const float*)d_in[8];
    const float* Who = (const float*)d_in[9];
    const float* bho = (const float*)d_in[10];
    const float* Whc = (const float*)d_in[11];
    const float* bhc = (const float*)d_in[12];
    const float* Wro = (const float*)d_in[13];
    const float* bro = (const float*)d_in[14];
    float* out = (float*)d_out;

    cudaFuncSetAttribute(lstm_persistent,
                         cudaFuncAttributeMaxDynamicSharedMemorySize, SMEM_TOTAL);

    repack_wh_frag<<<(G4/8) * 32 * 32 / 256, 256>>>(Whi, Whf, Who, Whc);
    repack_wx_frag<<<((G4/8) * 6 * 32 + 255) / 256, 256>>>(Wxi, Wxf, Wxo, Wxc);
    pack_bias<<<G4 / 256, 256>>>(bhi, bhf, bho, bhc);
    xcast_kernel<<<(TB * KXH + 255) / 256, 256>>>(x);
    lstm_persistent<<<dim3(32, 4), 256, SMEM_TOTAL>>>();
    readout_kernel<<<TB / 16, 256>>>(Wro, bro, out);
}